// round 1
// baseline (speedup 1.0000x reference)
#include <cuda_runtime.h>
#include <cstdint>

#define B_ 2
#define S_ 2048
#define D_ 1024
#define H_ 16
#define HD_ 64
#define FF_ 4096
#define MTOT (B_*S_)   // 4096 rows total

// ---------------- scratch (static device globals; no runtime allocation) ----
__device__ float g_x1  [MTOT*(size_t)D_];
__device__ float g_q   [MTOT*(size_t)D_];
__device__ float g_k   [MTOT*(size_t)D_];
__device__ float g_v   [MTOT*(size_t)D_];
__device__ float g_qr  [MTOT*(size_t)D_];
__device__ float g_kr  [MTOT*(size_t)D_];
__device__ float g_attn[MTOT*(size_t)D_];
__device__ float g_src2[MTOT*(size_t)D_];
__device__ float g_x2  [MTOT*(size_t)D_];
__device__ float g_gate[MTOT*(size_t)FF_];
__device__ float g_up  [MTOT*(size_t)FF_];

// ---------------- tf32 helpers ---------------------------------------------
__device__ __forceinline__ uint32_t f2tf(float x){
    uint32_t u; asm("cvt.rna.tf32.f32 %0, %1;" : "=r"(u) : "f"(x)); return u;
}
__device__ __forceinline__ void mma8(float c[4], const uint32_t a[4],
                                     uint32_t b0, uint32_t b1){
    asm volatile("mma.sync.aligned.m16n8k8.row.col.f32.tf32.tf32.f32 "
        "{%0,%1,%2,%3},{%4,%5,%6,%7},{%8,%9},{%0,%1,%2,%3};\n"
        : "+f"(c[0]), "+f"(c[1]), "+f"(c[2]), "+f"(c[3])
        : "r"(a[0]), "r"(a[1]), "r"(a[2]), "r"(a[3]), "r"(b0), "r"(b1));
}

// ---------------- generic TF32 GEMM: C[M,N] = A[M,K] * W[N,K]^T (+bias,+res)
// block tile 128x128, BK=32, 8 warps (4m x 2n), warp tile 32x64
#define LDT 36
__global__ __launch_bounds__(256) void gemm_tf32(
    const float* __restrict__ A, const float* __restrict__ W,
    const float* __restrict__ bias, const float* __restrict__ res,
    float* __restrict__ C, int M, int N, int K)
{
    __shared__ uint32_t As[128][LDT];
    __shared__ uint32_t Bs[128][LDT];
    const int tid = threadIdx.x;
    const int m0 = blockIdx.y * 128, n0 = blockIdx.x * 128;
    const int w = tid >> 5, lane = tid & 31, g = lane >> 2, t4 = lane & 3;
    const int wm = (w >> 1) * 32, wn = (w & 1) * 64;

    float acc[2][8][4];
    #pragma unroll
    for (int i=0;i<2;i++)
        #pragma unroll
        for (int j=0;j<8;j++)
            #pragma unroll
            for (int kk=0;kk<4;kk++) acc[i][j][kk]=0.f;

    const int r  = tid >> 3;          // 0..31
    const int c4 = (tid & 7) * 4;     // 0..28
    const float* Ag = A + (size_t)(m0 + r) * K + c4;
    const float* Wg = W + (size_t)(n0 + r) * K + c4;

    for (int kt = 0; kt < K; kt += 32){
        __syncthreads();
        #pragma unroll
        for (int i=0;i<4;i++){
            int rr = r + i*32;
            float4 va = *(const float4*)(Ag + (size_t)i*32*K + kt);
            float4 vb = *(const float4*)(Wg + (size_t)i*32*K + kt);
            uint4 ua = make_uint4(f2tf(va.x),f2tf(va.y),f2tf(va.z),f2tf(va.w));
            uint4 ub = make_uint4(f2tf(vb.x),f2tf(vb.y),f2tf(vb.z),f2tf(vb.w));
            *(uint4*)&As[rr][c4] = ua;
            *(uint4*)&Bs[rr][c4] = ub;
        }
        __syncthreads();
        #pragma unroll
        for (int ks = 0; ks < 32; ks += 8){
            uint32_t a0[4], a1[4];
            a0[0]=As[wm+g   ][ks+t4];   a0[1]=As[wm+g+8 ][ks+t4];
            a0[2]=As[wm+g   ][ks+t4+4]; a0[3]=As[wm+g+8 ][ks+t4+4];
            a1[0]=As[wm+16+g][ks+t4];   a1[1]=As[wm+24+g][ks+t4];
            a1[2]=As[wm+16+g][ks+t4+4]; a1[3]=As[wm+24+g][ks+t4+4];
            #pragma unroll
            for (int nt=0; nt<8; nt++){
                uint32_t b0 = Bs[wn+8*nt+g][ks+t4];
                uint32_t b1 = Bs[wn+8*nt+g][ks+t4+4];
                mma8(acc[0][nt], a0, b0, b1);
                mma8(acc[1][nt], a1, b0, b1);
            }
        }
    }

    #pragma unroll
    for (int mt=0; mt<2; mt++){
        int r0 = m0 + wm + 16*mt + g;
        #pragma unroll
        for (int nt=0; nt<8; nt++){
            int c = n0 + wn + 8*nt + 2*t4;
            float b0v = 0.f, b1v = 0.f;
            if (bias){ b0v = bias[c]; b1v = bias[c+1]; }
            size_t i0 = (size_t)r0 * N + c;
            size_t i1 = i0 + (size_t)8 * N;
            float v0 = acc[mt][nt][0] + b0v;
            float v1 = acc[mt][nt][1] + b1v;
            float v2 = acc[mt][nt][2] + b0v;
            float v3 = acc[mt][nt][3] + b1v;
            if (res){ v0 += res[i0]; v1 += res[i0+1]; v2 += res[i1]; v3 += res[i1+1]; }
            C[i0]   = v0; C[i0+1] = v1;
            C[i1]   = v2; C[i1+1] = v3;
        }
    }
}

// ---------------- LayerNorm (row of 1024, one block per row) ----------------
__global__ __launch_bounds__(256) void ln_kernel(
    const float* __restrict__ X, const float* __restrict__ gam,
    const float* __restrict__ bet, float* __restrict__ Y)
{
    int row = blockIdx.x; int tid = threadIdx.x;
    const float* x = X + (size_t)row * D_ + tid*4;
    float4 v = *(const float4*)x;
    float s  = v.x+v.y+v.z+v.w;
    float s2 = v.x*v.x+v.y*v.y+v.z*v.z+v.w*v.w;
    #pragma unroll
    for (int off=16; off; off>>=1){
        s  += __shfl_xor_sync(0xffffffffu, s,  off);
        s2 += __shfl_xor_sync(0xffffffffu, s2, off);
    }
    __shared__ float sh[16];
    int w = tid >> 5, lane = tid & 31;
    if (!lane){ sh[w] = s; sh[8+w] = s2; }
    __syncthreads();
    float st=0.f, st2=0.f;
    #pragma unroll
    for (int j=0;j<8;j++){ st += sh[j]; st2 += sh[8+j]; }
    float mu  = st * (1.f/1024.f);
    float var = st2 * (1.f/1024.f) - mu*mu;
    float inv = rsqrtf(var + 1e-5f);
    float4 gm = *(const float4*)(gam + tid*4);
    float4 bt = *(const float4*)(bet + tid*4);
    float4 y;
    y.x = (v.x-mu)*inv*gm.x + bt.x;
    y.y = (v.y-mu)*inv*gm.y + bt.y;
    y.z = (v.z-mu)*inv*gm.z + bt.z;
    y.w = (v.w-mu)*inv*gm.w + bt.w;
    *(float4*)(Y + (size_t)row * D_ + tid*4) = y;
}

// ---------------- RoPE on full d_model (rotate-half), q and k together ------
__global__ void rope_kernel(const float* __restrict__ Qi, const float* __restrict__ Ki,
                            const float* __restrict__ cs, const float* __restrict__ sn,
                            float* __restrict__ Qo, float* __restrict__ Ko)
{
    int i = blockIdx.x * blockDim.x + threadIdx.x;  // MTOT*512 threads
    int row = i >> 9;
    int d   = i & 511;
    int s   = row & (S_-1);
    float c0 = cs[(size_t)s*D_ + d],       s0 = sn[(size_t)s*D_ + d];
    float c1 = cs[(size_t)s*D_ + d + 512], s1 = sn[(size_t)s*D_ + d + 512];
    size_t base = (size_t)row * D_;
    float qa = Qi[base+d], qb = Qi[base+d+512];
    Qo[base+d]     = qa*c0 - qb*s0;
    Qo[base+d+512] = qb*c1 + qa*s1;
    float ka = Ki[base+d], kb = Ki[base+d+512];
    Ko[base+d]     = ka*c0 - kb*s0;
    Ko[base+d+512] = kb*c1 + ka*s1;
}

// ---------------- Flash attention, TF32 mma, 64-row q tiles -----------------
#define LDK 68
#define LDV 72
__global__ __launch_bounds__(128) void attn_kernel(
    const float* __restrict__ Q, const float* __restrict__ Kg,
    const float* __restrict__ Vg, float* __restrict__ O)
{
    __shared__ uint32_t Ks[64][LDK];
    __shared__ uint32_t Vs[64][LDV];
    const int tid = threadIdx.x;
    const int w = tid >> 5, lane = tid & 31, g = lane >> 2, t4 = lane & 3;
    const int bh = blockIdx.y, b = bh >> 4, h = bh & 15;
    const int q0 = blockIdx.x * 64;
    const int rr = tid >> 4;            // 0..7
    const int cc4 = (tid & 15) * 4;     // 0..60

    // stage Q (scaled by 1/sqrt(HD)) into Ks, pull fragments to registers
    const float* qbase = Q + ((size_t)(b*S_ + q0)) * D_ + h*HD_;
    #pragma unroll
    for (int i=0;i<8;i++){
        int row = rr + i*8;
        float4 v = *(const float4*)(qbase + (size_t)row*D_ + cc4);
        uint4 u = make_uint4(f2tf(v.x*0.125f), f2tf(v.y*0.125f),
                             f2tf(v.z*0.125f), f2tf(v.w*0.125f));
        *(uint4*)&Ks[row][cc4] = u;
    }
    __syncthreads();
    uint32_t qf[8][4];
    const int qm = w * 16;
    #pragma unroll
    for (int ks=0; ks<8; ks++){
        qf[ks][0] = Ks[qm+g  ][8*ks+t4];
        qf[ks][1] = Ks[qm+g+8][8*ks+t4];
        qf[ks][2] = Ks[qm+g  ][8*ks+t4+4];
        qf[ks][3] = Ks[qm+g+8][8*ks+t4+4];
    }

    float o[8][4];
    #pragma unroll
    for (int i=0;i<8;i++){ o[i][0]=0.f; o[i][1]=0.f; o[i][2]=0.f; o[i][3]=0.f; }
    float mrow0=-1e30f, mrow1=-1e30f, l0=0.f, l1=0.f;

    for (int kt=0; kt<S_/64; kt++){
        __syncthreads();
        const float* kb = Kg + ((size_t)(b*S_ + kt*64)) * D_ + h*HD_;
        const float* vb = Vg + ((size_t)(b*S_ + kt*64)) * D_ + h*HD_;
        #pragma unroll
        for (int i=0;i<8;i++){
            int row = rr + i*8;
            float4 v = *(const float4*)(kb + (size_t)row*D_ + cc4);
            *(uint4*)&Ks[row][cc4] = make_uint4(f2tf(v.x),f2tf(v.y),f2tf(v.z),f2tf(v.w));
            float4 u = *(const float4*)(vb + (size_t)row*D_ + cc4);
            *(uint4*)&Vs[row][cc4] = make_uint4(f2tf(u.x),f2tf(u.y),f2tf(u.z),f2tf(u.w));
        }
        __syncthreads();

        // S = Q K^T (16 rows per warp x 64 keys)
        float s[8][4];
        #pragma unroll
        for (int i=0;i<8;i++){ s[i][0]=0.f; s[i][1]=0.f; s[i][2]=0.f; s[i][3]=0.f; }
        #pragma unroll
        for (int ks=0; ks<8; ks++){
            #pragma unroll
            for (int nt=0; nt<8; nt++){
                uint32_t b0 = Ks[8*nt+g][8*ks+t4];
                uint32_t b1 = Ks[8*nt+g][8*ks+t4+4];
                mma8(s[nt], qf[ks], b0, b1);
            }
        }

        // online softmax
        float mt0=-1e30f, mt1=-1e30f;
        #pragma unroll
        for (int nt=0; nt<8; nt++){
            mt0 = fmaxf(mt0, fmaxf(s[nt][0], s[nt][1]));
            mt1 = fmaxf(mt1, fmaxf(s[nt][2], s[nt][3]));
        }
        mt0 = fmaxf(mt0, __shfl_xor_sync(0xffffffffu, mt0, 1));
        mt0 = fmaxf(mt0, __shfl_xor_sync(0xffffffffu, mt0, 2));
        mt1 = fmaxf(mt1, __shfl_xor_sync(0xffffffffu, mt1, 1));
        mt1 = fmaxf(mt1, __shfl_xor_sync(0xffffffffu, mt1, 2));
        float mn0 = fmaxf(mrow0, mt0), mn1 = fmaxf(mrow1, mt1);
        float al0 = __expf(mrow0 - mn0), al1 = __expf(mrow1 - mn1);
        float rs0 = 0.f, rs1 = 0.f;
        #pragma unroll
        for (int nt=0; nt<8; nt++){
            s[nt][0] = __expf(s[nt][0]-mn0);
            s[nt][1] = __expf(s[nt][1]-mn0);
            s[nt][2] = __expf(s[nt][2]-mn1);
            s[nt][3] = __expf(s[nt][3]-mn1);
            rs0 += s[nt][0] + s[nt][1];
            rs1 += s[nt][2] + s[nt][3];
        }
        rs0 += __shfl_xor_sync(0xffffffffu, rs0, 1);
        rs0 += __shfl_xor_sync(0xffffffffu, rs0, 2);
        rs1 += __shfl_xor_sync(0xffffffffu, rs1, 1);
        rs1 += __shfl_xor_sync(0xffffffffu, rs1, 2);
        l0 = l0*al0 + rs0;  l1 = l1*al1 + rs1;
        mrow0 = mn0; mrow1 = mn1;
        #pragma unroll
        for (int nt=0; nt<8; nt++){
            o[nt][0]*=al0; o[nt][1]*=al0; o[nt][2]*=al1; o[nt][3]*=al1;
        }

        // O += P V  (P in registers -> A fragments via quad shuffles)
        #pragma unroll
        for (int ks=0; ks<8; ks++){
            int srcA = (g<<2) + (t4>>1);
            int srcB = srcA + 2;
            float p00 = __shfl_sync(0xffffffffu, s[ks][0], srcA);
            float p01 = __shfl_sync(0xffffffffu, s[ks][1], srcA);
            float p02 = __shfl_sync(0xffffffffu, s[ks][0], srcB);
            float p03 = __shfl_sync(0xffffffffu, s[ks][1], srcB);
            float p10 = __shfl_sync(0xffffffffu, s[ks][2], srcA);
            float p11 = __shfl_sync(0xffffffffu, s[ks][3], srcA);
            float p12 = __shfl_sync(0xffffffffu, s[ks][2], srcB);
            float p13 = __shfl_sync(0xffffffffu, s[ks][3], srcB);
            bool odd = (t4 & 1);
            uint32_t a[4];
            a[0] = f2tf(odd ? p01 : p00);
            a[1] = f2tf(odd ? p11 : p10);
            a[2] = f2tf(odd ? p03 : p02);
            a[3] = f2tf(odd ? p13 : p12);
            #pragma unroll
            for (int nt=0; nt<8; nt++){
                uint32_t b0 = Vs[8*ks+t4  ][8*nt+g];
                uint32_t b1 = Vs[8*ks+t4+4][8*nt+g];
                mma8(o[nt], a, b0, b1);
            }
        }
    }

    float inv0 = 1.f/l0, inv1 = 1.f/l1;
    float* ob0 = O + ((size_t)(b*S_ + q0 + qm + g)) * D_ + h*HD_;
    float* ob1 = ob0 + (size_t)8 * D_;
    #pragma unroll
    for (int nt=0; nt<8; nt++){
        int c = 8*nt + 2*t4;
        ob0[c]   = o[nt][0]*inv0;
        ob0[c+1] = o[nt][1]*inv0;
        ob1[c]   = o[nt][2]*inv1;
        ob1[c+1] = o[nt][3]*inv1;
    }
}

// ---------------- SiLU(gate) * up, in place into gate -----------------------
__global__ void silu_kernel(float* __restrict__ gate, const float* __restrict__ up){
    size_t i = ((size_t)blockIdx.x * blockDim.x + threadIdx.x) * 4;
    float4 gv = *(float4*)(gate + i);
    float4 uv = *(const float4*)(up + i);
    gv.x = gv.x * uv.x / (1.f + __expf(-gv.x));
    gv.y = gv.y * uv.y / (1.f + __expf(-gv.y));
    gv.z = gv.z * uv.z / (1.f + __expf(-gv.z));
    gv.w = gv.w * uv.w / (1.f + __expf(-gv.w));
    *(float4*)(gate + i) = gv;
}

// ---------------- launch ----------------------------------------------------
extern "C" void kernel_launch(void* const* d_in, const int* in_sizes, int n_in,
                              void* d_out, int out_size)
{
    const float* src = (const float*)d_in[0];
    const float* cs  = (const float*)d_in[1];
    const float* sn  = (const float*)d_in[2];
    // d_in[3] = src_key_padding_mask (all false in this problem; softmax unmasked)
    const float* Wq = (const float*)d_in[4];
    const float* bq = (const float*)d_in[5];
    const float* Wk = (const float*)d_in[6];
    const float* bk = (const float*)d_in[7];
    const float* Wv = (const float*)d_in[8];
    const float* bv = (const float*)d_in[9];
    const float* Wo = (const float*)d_in[10];
    const float* bo = (const float*)d_in[11];
    const float* g1 = (const float*)d_in[12];
    const float* b1 = (const float*)d_in[13];
    const float* g2 = (const float*)d_in[14];
    const float* b2 = (const float*)d_in[15];
    const float* W1 = (const float*)d_in[16];
    const float* W3 = (const float*)d_in[17];
    const float* W2 = (const float*)d_in[18];
    float* out = (float*)d_out;

    float *x1,*q,*k,*v,*qr,*kr,*attn,*src2,*x2,*gate,*up;
    cudaGetSymbolAddress((void**)&x1,   g_x1);
    cudaGetSymbolAddress((void**)&q,    g_q);
    cudaGetSymbolAddress((void**)&k,    g_k);
    cudaGetSymbolAddress((void**)&v,    g_v);
    cudaGetSymbolAddress((void**)&qr,   g_qr);
    cudaGetSymbolAddress((void**)&kr,   g_kr);
    cudaGetSymbolAddress((void**)&attn, g_attn);
    cudaGetSymbolAddress((void**)&src2, g_src2);
    cudaGetSymbolAddress((void**)&x2,   g_x2);
    cudaGetSymbolAddress((void**)&gate, g_gate);
    cudaGetSymbolAddress((void**)&up,   g_up);

    // 1) LN1
    ln_kernel<<<MTOT, 256>>>(src, g1, b1, x1);

    // 2) QKV projections
    dim3 gqkv(D_/128, MTOT/128);
    gemm_tf32<<<gqkv, 256>>>(x1, Wq, bq, nullptr, q, MTOT, D_, D_);
    gemm_tf32<<<gqkv, 256>>>(x1, Wk, bk, nullptr, k, MTOT, D_, D_);
    gemm_tf32<<<gqkv, 256>>>(x1, Wv, bv, nullptr, v, MTOT, D_, D_);

    // 3) RoPE on q,k (full d_model, pre-head-split)
    rope_kernel<<<(MTOT*512)/256, 256>>>(q, k, cs, sn, qr, kr);

    // 4) flash attention
    dim3 ga(S_/64, B_*H_);
    attn_kernel<<<ga, 128>>>(qr, kr, v, attn);

    // 5) O projection + bias + residual(src) -> src2
    gemm_tf32<<<gqkv, 256>>>(attn, Wo, bo, src, src2, MTOT, D_, D_);

    // 6) LN2
    ln_kernel<<<MTOT, 256>>>(src2, g2, b2, x2);

    // 7) FFN gate/up
    dim3 gff(FF_/128, MTOT/128);
    gemm_tf32<<<gff, 256>>>(x2, W1, nullptr, nullptr, gate, MTOT, FF_, D_);
    gemm_tf32<<<gff, 256>>>(x2, W3, nullptr, nullptr, up,   MTOT, FF_, D_);

    // 8) h = silu(gate)*up (in place into gate)
    silu_kernel<<<(MTOT*(size_t)FF_/4)/256, 256>>>(gate, up);

    // 9) down projection + residual(src2) -> out
    gemm_tf32<<<gqkv, 256>>>(gate, W2, nullptr, src2, out, MTOT, D_, FF_);
}